// round 4
// baseline (speedup 1.0000x reference)
#include <cuda_runtime.h>
#include <cuda_bf16.h>

#define N_NODES 100000
#define F_IN 128
#define H 16

// ---------------- device scratch (no allocations allowed) ----------------
__device__ __align__(16) float g_y1 [N_NODES * H];  // x @ W1l
__device__ __align__(16) float g_s1 [N_NODES * H];  // x @ W1r
__device__ __align__(16) float g_acc1[N_NODES * H];
__device__ __align__(16) float g_cnt [N_NODES];
__device__ __align__(16) float g_y2 [N_NODES * H];  // h1 @ W2l
__device__ __align__(16) float g_s2 [N_NODES * H];  // h1 @ W2r
__device__ __align__(16) float g_acc2[N_NODES * H];
__device__ __align__(16) float g_h2 [N_NODES * H];

// index dtype flags: 1 if the corresponding index tensor is int64
__device__ int g_ei64;
__device__ int g_di64;

// sm_90+ vector reduction: 4 floats in one L2 atomic op
__device__ __forceinline__ void red_add_v4(float* addr, float4 v) {
    asm volatile("red.global.add.v4.f32 [%0], {%1, %2, %3, %4};"
                 :: "l"(addr), "f"(v.x), "f"(v.y), "f"(v.z), "f"(v.w)
                 : "memory");
}
__device__ __forceinline__ void red_add_f32(float* addr, float v) {
    asm volatile("red.global.add.f32 [%0], %1;"
                 :: "l"(addr), "f"(v) : "memory");
}

// ---------------- dtype probe + zero accumulators ------------------------
// int64 non-negative indices -> every odd 32-bit word is 0.
// int32 random indices in [0,1e5) -> P(16 odd words all zero) ~ 1e-80.
__global__ void k_zero(const int* __restrict__ ei32, const int* __restrict__ di32) {
    int i = blockIdx.x * blockDim.x + threadIdx.x;
    if (i == 0) {
        int e64 = 1, d64 = 1;
#pragma unroll
        for (int k = 0; k < 16; k++) {
            if (ei32[2 * k + 1] != 0) e64 = 0;
            if (di32[2 * k + 1] != 0) d64 = 0;
        }
        g_ei64 = e64;
        g_di64 = d64;
    }
    int stride = gridDim.x * blockDim.x;
    for (int j = i; j < N_NODES * H; j += stride) {
        g_acc1[j] = 0.0f;
        g_acc2[j] = 0.0f;
    }
    for (int j = i; j < N_NODES; j += stride) g_cnt[j] = 0.0f;
}

// ---------------- proj1: y1 = x@W1l, s1 = x@W1r (fused, reg-tiled) -------
__global__ void __launch_bounds__(256) k_proj1(const float* __restrict__ x,
                                               const float* __restrict__ W1l,
                                               const float* __restrict__ W1r) {
    __shared__ float wc[F_IN][32];   // [k][f], f in [0,32): L then R
    int t = threadIdx.x;
    for (int i = t; i < F_IN * H; i += 256) {
        int k = i >> 4, f = i & 15;
        wc[k][f]      = W1l[i];
        wc[k][f + 16] = W1r[i];
    }
    __syncthreads();

    int fg = t & 3;            // output quad-group: fg*8 .. fg*8+7
    int ng = t >> 2;           // 0..63
    int node0 = (blockIdx.x * 64 + ng) * 4;

    bool v[4];
#pragma unroll
    for (int n = 0; n < 4; n++) v[n] = (node0 + n) < N_NODES;

    float acc[4][8];
#pragma unroll
    for (int n = 0; n < 4; n++)
#pragma unroll
        for (int f = 0; f < 8; f++) acc[n][f] = 0.0f;

    const float4* xp = reinterpret_cast<const float4*>(x);

    for (int k4 = 0; k4 < F_IN / 4; k4++) {
        float4 xv[4];
#pragma unroll
        for (int n = 0; n < 4; n++)
            xv[n] = v[n] ? xp[(size_t)(node0 + n) * (F_IN / 4) + k4]
                         : make_float4(0.f, 0.f, 0.f, 0.f);
#pragma unroll
        for (int kk = 0; kk < 4; kk++) {
            const float4 wA = *reinterpret_cast<const float4*>(&wc[k4 * 4 + kk][fg * 8]);
            const float4 wB = *reinterpret_cast<const float4*>(&wc[k4 * 4 + kk][fg * 8 + 4]);
#pragma unroll
            for (int n = 0; n < 4; n++) {
                float xs = (kk == 0) ? xv[n].x : (kk == 1) ? xv[n].y
                         : (kk == 2) ? xv[n].z : xv[n].w;
                acc[n][0] = fmaf(xs, wA.x, acc[n][0]);
                acc[n][1] = fmaf(xs, wA.y, acc[n][1]);
                acc[n][2] = fmaf(xs, wA.z, acc[n][2]);
                acc[n][3] = fmaf(xs, wA.w, acc[n][3]);
                acc[n][4] = fmaf(xs, wB.x, acc[n][4]);
                acc[n][5] = fmaf(xs, wB.y, acc[n][5]);
                acc[n][6] = fmaf(xs, wB.z, acc[n][6]);
                acc[n][7] = fmaf(xs, wB.w, acc[n][7]);
            }
        }
    }

#pragma unroll
    for (int n = 0; n < 4; n++) {
        if (!v[n]) continue;
        int node = node0 + n;
        float* dst = (fg < 2) ? &g_y1[node * H + fg * 8]
                              : &g_s1[node * H + (fg - 2) * 8];
        float4* d4 = reinterpret_cast<float4*>(dst);
        d4[0] = make_float4(acc[n][0], acc[n][1], acc[n][2], acc[n][3]);
        d4[1] = make_float4(acc[n][4], acc[n][5], acc[n][6], acc[n][7]);
    }
}

// ---------------- edge index fetch (dtype-flexible) ----------------------
__device__ __forceinline__ void load_edge(const void* eiv, int e, int E, int is64,
                                          int& src, int& dst) {
    if (is64) {
        const long long* ei = (const long long*)eiv;
        src = (int)ei[e];
        dst = (int)ei[E + e];
    } else {
        const int* ei = (const int*)eiv;
        src = ei[e];
        dst = ei[E + e];
    }
}

// ---------------- scatter pass 1: acc1[dst] += y1[src], cnt[dst]++ -------
__global__ void k_scatter1(const void* __restrict__ eiv, int E) {
    int e = blockIdx.x * blockDim.x + threadIdx.x;
    if (e >= E) return;
    int src, dst;
    load_edge(eiv, e, E, g_ei64, src, dst);
    const float4* yp = reinterpret_cast<const float4*>(g_y1 + (size_t)src * H);
    float* ap = g_acc1 + (size_t)dst * H;
    float4 v0 = yp[0], v1 = yp[1], v2 = yp[2], v3 = yp[3];
    red_add_v4(ap,      v0);
    red_add_v4(ap + 4,  v1);
    red_add_v4(ap + 8,  v2);
    red_add_v4(ap + 12, v3);
    red_add_f32(&g_cnt[dst], 1.0f);
}

// ---------------- h1 = relu(acc1/cnt + b1 + s1); y2 = h1@W2l; s2 = h1@W2r
__global__ void __launch_bounds__(256) k_h1proj2(const float* __restrict__ b1,
                                                 const float* __restrict__ W2l,
                                                 const float* __restrict__ W2r) {
    __shared__ float w2[H][32];   // [k][f]: L then R
    __shared__ float sb1[H];
    int t = threadIdx.x;
    if (t < H * H) {
        int k = t >> 4, f = t & 15;
        w2[k][f]      = W2l[t];
        w2[k][f + 16] = W2r[t];
    }
    if (t < H) sb1[t] = b1[t];
    __syncthreads();

    int node = blockIdx.x * 256 + t;
    if (node >= N_NODES) return;

    float inv = 1.0f / fmaxf(g_cnt[node], 1.0f);
    const float4* a4 = reinterpret_cast<const float4*>(g_acc1 + (size_t)node * H);
    const float4* s4 = reinterpret_cast<const float4*>(g_s1  + (size_t)node * H);

    float h[H];
#pragma unroll
    for (int q = 0; q < 4; q++) {
        float4 a = a4[q], s = s4[q];
        h[q * 4 + 0] = fmaxf(a.x * inv + sb1[q * 4 + 0] + s.x, 0.0f);
        h[q * 4 + 1] = fmaxf(a.y * inv + sb1[q * 4 + 1] + s.y, 0.0f);
        h[q * 4 + 2] = fmaxf(a.z * inv + sb1[q * 4 + 2] + s.z, 0.0f);
        h[q * 4 + 3] = fmaxf(a.w * inv + sb1[q * 4 + 3] + s.w, 0.0f);
    }

    float yo[H], so[H];
#pragma unroll
    for (int f = 0; f < H; f++) { yo[f] = 0.0f; so[f] = 0.0f; }
#pragma unroll
    for (int k = 0; k < H; k++) {
        float hk = h[k];
#pragma unroll
        for (int q = 0; q < 4; q++) {
            float4 wl = *reinterpret_cast<const float4*>(&w2[k][q * 4]);
            float4 wr = *reinterpret_cast<const float4*>(&w2[k][16 + q * 4]);
            yo[q * 4 + 0] = fmaf(hk, wl.x, yo[q * 4 + 0]);
            yo[q * 4 + 1] = fmaf(hk, wl.y, yo[q * 4 + 1]);
            yo[q * 4 + 2] = fmaf(hk, wl.z, yo[q * 4 + 2]);
            yo[q * 4 + 3] = fmaf(hk, wl.w, yo[q * 4 + 3]);
            so[q * 4 + 0] = fmaf(hk, wr.x, so[q * 4 + 0]);
            so[q * 4 + 1] = fmaf(hk, wr.y, so[q * 4 + 1]);
            so[q * 4 + 2] = fmaf(hk, wr.z, so[q * 4 + 2]);
            so[q * 4 + 3] = fmaf(hk, wr.w, so[q * 4 + 3]);
        }
    }
    float4* y4 = reinterpret_cast<float4*>(g_y2 + (size_t)node * H);
    float4* o4 = reinterpret_cast<float4*>(g_s2 + (size_t)node * H);
#pragma unroll
    for (int q = 0; q < 4; q++) {
        y4[q] = make_float4(yo[q * 4], yo[q * 4 + 1], yo[q * 4 + 2], yo[q * 4 + 3]);
        o4[q] = make_float4(so[q * 4], so[q * 4 + 1], so[q * 4 + 2], so[q * 4 + 3]);
    }
}

// ---------------- scatter pass 2: acc2[dst] += y2[src] -------------------
__global__ void k_scatter2(const void* __restrict__ eiv, int E) {
    int e = blockIdx.x * blockDim.x + threadIdx.x;
    if (e >= E) return;
    int src, dst;
    load_edge(eiv, e, E, g_ei64, src, dst);
    const float4* yp = reinterpret_cast<const float4*>(g_y2 + (size_t)src * H);
    float* ap = g_acc2 + (size_t)dst * H;
    float4 v0 = yp[0], v1 = yp[1], v2 = yp[2], v3 = yp[3];
    red_add_v4(ap,      v0);
    red_add_v4(ap + 4,  v1);
    red_add_v4(ap + 8,  v2);
    red_add_v4(ap + 12, v3);
}

// ---------------- h2 = acc2/cnt + b2 + s2 (no relu) ----------------------
__global__ void __launch_bounds__(256) k_h2(const float* __restrict__ b2) {
    __shared__ float sb2[H];
    int t = threadIdx.x;
    if (t < H) sb2[t] = b2[t];
    __syncthreads();

    int node = blockIdx.x * 256 + t;
    if (node >= N_NODES) return;

    float inv = 1.0f / fmaxf(g_cnt[node], 1.0f);
    const float4* a4 = reinterpret_cast<const float4*>(g_acc2 + (size_t)node * H);
    const float4* s4 = reinterpret_cast<const float4*>(g_s2  + (size_t)node * H);
    float4* o4 = reinterpret_cast<float4*>(g_h2 + (size_t)node * H);
#pragma unroll
    for (int q = 0; q < 4; q++) {
        float4 a = a4[q], s = s4[q];
        o4[q] = make_float4(a.x * inv + sb2[q * 4 + 0] + s.x,
                            a.y * inv + sb2[q * 4 + 1] + s.y,
                            a.z * inv + sb2[q * 4 + 2] + s.z,
                            a.w * inv + sb2[q * 4 + 3] + s.w);
    }
}

// ---------------- decode: sigmoid(<h2[i], h2[j]>) ------------------------
__global__ void __launch_bounds__(256) k_decode(const void* __restrict__ div,
                                                int P, float* __restrict__ out) {
    int p = blockIdx.x * blockDim.x + threadIdx.x;
    if (p >= P) return;
    int i, j;
    if (g_di64) {
        const long long* di = (const long long*)div;
        i = (int)di[p];
        j = (int)di[P + p];
    } else {
        const int* di = (const int*)div;
        i = di[p];
        j = di[P + p];
    }
    const float4* a = reinterpret_cast<const float4*>(g_h2 + (size_t)i * H);
    const float4* b = reinterpret_cast<const float4*>(g_h2 + (size_t)j * H);
    float s = 0.0f;
#pragma unroll
    for (int q = 0; q < 4; q++) {
        float4 av = a[q], bv = b[q];
        s = fmaf(av.x, bv.x, s);
        s = fmaf(av.y, bv.y, s);
        s = fmaf(av.z, bv.z, s);
        s = fmaf(av.w, bv.w, s);
    }
    out[p] = 1.0f / (1.0f + __expf(-s));
}

// ---------------- launch ---------------------------------------------------
extern "C" void kernel_launch(void* const* d_in, const int* in_sizes, int n_in,
                              void* d_out, int out_size) {
    const float* x   = (const float*)d_in[0];
    const float* W1l = (const float*)d_in[1];
    const float* b1  = (const float*)d_in[2];
    const float* W1r = (const float*)d_in[3];
    const float* W2l = (const float*)d_in[4];
    const float* b2  = (const float*)d_in[5];
    const float* W2r = (const float*)d_in[6];
    const void*  ei  = d_in[7];
    const void*  di  = d_in[8];
    float* out = (float*)d_out;

    int E = in_sizes[7] / 2;
    int P = in_sizes[8] / 2;

    k_zero<<<2048, 256>>>((const int*)ei, (const int*)di);
    k_proj1<<<(N_NODES + 255) / 256, 256>>>(x, W1l, W1r);
    k_scatter1<<<(E + 255) / 256, 256>>>(ei, E);
    k_h1proj2<<<(N_NODES + 255) / 256, 256>>>(b1, W2l, W2r);
    k_scatter2<<<(E + 255) / 256, 256>>>(ei, E);
    k_h2<<<(N_NODES + 255) / 256, 256>>>(b2);
    k_decode<<<(P + 255) / 256, 256>>>(di, P, out);
}

// round 9
// speedup vs baseline: 1.1833x; 1.1833x over previous
#include <cuda_runtime.h>
#include <cuda_bf16.h>

#define N_NODES 100000
#define F_IN 128
#define H 16

// ---------------- device scratch (no allocations allowed) ----------------
__device__ __align__(16) float g_y1 [N_NODES * H];  // x @ W1l
__device__ __align__(16) float g_s1 [N_NODES * H];  // x @ W1r
__device__ __align__(16) float g_acc1[N_NODES * H];
__device__ __align__(16) float g_cnt [N_NODES];
__device__ __align__(16) float g_y2 [N_NODES * H];  // h1 @ W2l
__device__ __align__(16) float g_s2 [N_NODES * H];  // h1 @ W2r
__device__ __align__(16) float g_acc2[N_NODES * H];
__device__ __align__(16) float g_h2 [N_NODES * H];

// index dtype flags: 1 if the corresponding index tensor is int64
__device__ int g_ei64;
__device__ int g_di64;

// sm_90+ vector reduction: 4 floats in one L2 atomic op
__device__ __forceinline__ void red_add_v4(float* addr, float4 v) {
    asm volatile("red.global.add.v4.f32 [%0], {%1, %2, %3, %4};"
                 :: "l"(addr), "f"(v.x), "f"(v.y), "f"(v.z), "f"(v.w)
                 : "memory");
}
__device__ __forceinline__ void red_add_f32(float* addr, float v) {
    asm volatile("red.global.add.f32 [%0], %1;"
                 :: "l"(addr), "f"(v) : "memory");
}

// ---------------- proj1: y1 = x@W1l, s1 = x@W1r; zero acc1/cnt; probe ----
// Block: 256 threads, 256 nodes/block.
__global__ void __launch_bounds__(256) k_proj1(const float* __restrict__ x,
                                               const float* __restrict__ W1l,
                                               const float* __restrict__ W1r,
                                               const int* __restrict__ ei32,
                                               const int* __restrict__ di32) {
    __shared__ float wc[F_IN][32];   // [k][f], f in [0,32): L then R
    int t = threadIdx.x;

    // dtype probe: int64 non-negative -> odd 32-bit words are 0.
    if (blockIdx.x == 0 && t == 0) {
        int e64 = 1, d64 = 1;
#pragma unroll
        for (int k = 0; k < 16; k++) {
            if (ei32[2 * k + 1] != 0) e64 = 0;
            if (di32[2 * k + 1] != 0) d64 = 0;
        }
        g_ei64 = e64;
        g_di64 = d64;
    }

    // zero acc1 + cnt for this block's nodes
    {
        int node = blockIdx.x * 256 + t;
        if (node < N_NODES) {
            float4* a4 = reinterpret_cast<float4*>(g_acc1 + (size_t)node * H);
            float4 z = make_float4(0.f, 0.f, 0.f, 0.f);
            a4[0] = z; a4[1] = z; a4[2] = z; a4[3] = z;
            g_cnt[node] = 0.0f;
        }
    }

    // stage weights: 256 threads, each writes its W1l[i] and W1r[i] entry
    for (int i = t; i < F_IN * H; i += 256) {
        int k = i >> 4, f = i & 15;
        wc[k][f]      = W1l[i];
        wc[k][f + 16] = W1r[i];
    }
    __syncthreads();

    int fg = t & 3;            // output quad-group: fg*8 .. fg*8+7
    int ng = t >> 2;           // 0..63
    int node0 = (blockIdx.x * 64 + ng) * 4;

    bool v[4];
#pragma unroll
    for (int n = 0; n < 4; n++) v[n] = (node0 + n) < N_NODES;

    float acc[4][8];
#pragma unroll
    for (int n = 0; n < 4; n++)
#pragma unroll
        for (int f = 0; f < 8; f++) acc[n][f] = 0.0f;

    const float4* xp = reinterpret_cast<const float4*>(x);

    for (int k4 = 0; k4 < F_IN / 4; k4++) {
        float4 xv[4];
#pragma unroll
        for (int n = 0; n < 4; n++)
            xv[n] = v[n] ? xp[(size_t)(node0 + n) * (F_IN / 4) + k4]
                         : make_float4(0.f, 0.f, 0.f, 0.f);
#pragma unroll
        for (int kk = 0; kk < 4; kk++) {
            const float4 wA = *reinterpret_cast<const float4*>(&wc[k4 * 4 + kk][fg * 8]);
            const float4 wB = *reinterpret_cast<const float4*>(&wc[k4 * 4 + kk][fg * 8 + 4]);
#pragma unroll
            for (int n = 0; n < 4; n++) {
                float xs = (kk == 0) ? xv[n].x : (kk == 1) ? xv[n].y
                         : (kk == 2) ? xv[n].z : xv[n].w;
                acc[n][0] = fmaf(xs, wA.x, acc[n][0]);
                acc[n][1] = fmaf(xs, wA.y, acc[n][1]);
                acc[n][2] = fmaf(xs, wA.z, acc[n][2]);
                acc[n][3] = fmaf(xs, wA.w, acc[n][3]);
                acc[n][4] = fmaf(xs, wB.x, acc[n][4]);
                acc[n][5] = fmaf(xs, wB.y, acc[n][5]);
                acc[n][6] = fmaf(xs, wB.z, acc[n][6]);
                acc[n][7] = fmaf(xs, wB.w, acc[n][7]);
            }
        }
    }

#pragma unroll
    for (int n = 0; n < 4; n++) {
        if (!v[n]) continue;
        int node = node0 + n;
        float* dst = (fg < 2) ? &g_y1[node * H + fg * 8]
                              : &g_s1[node * H + (fg - 2) * 8];
        float4* d4 = reinterpret_cast<float4*>(dst);
        d4[0] = make_float4(acc[n][0], acc[n][1], acc[n][2], acc[n][3]);
        d4[1] = make_float4(acc[n][4], acc[n][5], acc[n][6], acc[n][7]);
    }
}

// ---------------- scatter: 4 threads per edge ----------------------------
// q = lane&3 handles floats [q*4, q*4+4) of the 16-float payload.
// Lane q==0 loads (src,dst), broadcast via shfl within the 4-lane group.
template<bool WITH_CNT>
__device__ __forceinline__ void scatter_body(const void* __restrict__ eiv, int E,
                                             const float* __restrict__ ysrc,
                                             float* __restrict__ adst) {
    int gid = blockIdx.x * blockDim.x + threadIdx.x;
    int e = gid >> 2;
    int q = gid & 3;
    if (e >= E) return;
    unsigned mask = __activemask();
    int lane = threadIdx.x & 31;

    int src = 0, dst = 0;
    if (q == 0) {
        if (g_ei64) {
            const long long* ei = (const long long*)eiv;
            src = (int)ei[e];
            dst = (int)ei[E + e];
        } else {
            const int* ei = (const int*)eiv;
            src = ei[e];
            dst = ei[E + e];
        }
    }
    src = __shfl_sync(mask, src, lane & ~3);
    dst = __shfl_sync(mask, dst, lane & ~3);

    float4 v = reinterpret_cast<const float4*>(ysrc)[(size_t)src * 4 + q];
    red_add_v4(adst + (size_t)dst * H + q * 4, v);
    if (WITH_CNT && q == 0) red_add_f32(&g_cnt[dst], 1.0f);
}

__global__ void __launch_bounds__(256) k_scatter1(const void* __restrict__ eiv, int E) {
    scatter_body<true>(eiv, E, g_y1, g_acc1);
}
__global__ void __launch_bounds__(256) k_scatter2(const void* __restrict__ eiv, int E) {
    scatter_body<false>(eiv, E, g_y2, g_acc2);
}

// ---- h1 = relu(acc1/cnt + b1 + s1); y2/s2 = h1@W2{l,r}; zero acc2 -------
// 2 threads per node: side = gid&1 computes one of the two 16-wide GEMVs.
__global__ void __launch_bounds__(256) k_h1proj2(const float* __restrict__ b1,
                                                 const float* __restrict__ W2l,
                                                 const float* __restrict__ W2r) {
    __shared__ float w2[H][32];   // [k][f]: L then R
    __shared__ float sb1[H];
    int t = threadIdx.x;
    {   // H*H = 256 == blockDim: each thread stages one entry of each matrix
        int k = t >> 4, f = t & 15;
        w2[k][f]      = W2l[t];
        w2[k][f + 16] = W2r[t];
    }
    if (t < H) sb1[t] = b1[t];
    __syncthreads();

    int gid = blockIdx.x * 256 + t;
    int node = gid >> 1;
    int side = gid & 1;
    if (node >= N_NODES) return;

    // zero acc2: each side zeroes half the node row
    {
        float4* a4 = reinterpret_cast<float4*>(g_acc2 + (size_t)node * H) + side * 2;
        float4 z = make_float4(0.f, 0.f, 0.f, 0.f);
        a4[0] = z; a4[1] = z;
    }

    float inv = 1.0f / fmaxf(g_cnt[node], 1.0f);
    const float4* a4 = reinterpret_cast<const float4*>(g_acc1 + (size_t)node * H);
    const float4* s4 = reinterpret_cast<const float4*>(g_s1  + (size_t)node * H);

    float h[H];
#pragma unroll
    for (int q = 0; q < 4; q++) {
        float4 a = a4[q], s = s4[q];
        h[q * 4 + 0] = fmaxf(a.x * inv + sb1[q * 4 + 0] + s.x, 0.0f);
        h[q * 4 + 1] = fmaxf(a.y * inv + sb1[q * 4 + 1] + s.y, 0.0f);
        h[q * 4 + 2] = fmaxf(a.z * inv + sb1[q * 4 + 2] + s.z, 0.0f);
        h[q * 4 + 3] = fmaxf(a.w * inv + sb1[q * 4 + 3] + s.w, 0.0f);
    }

    float o[H];
#pragma unroll
    for (int f = 0; f < H; f++) o[f] = 0.0f;
    int wofs = side * 16;
#pragma unroll
    for (int k = 0; k < H; k++) {
        float hk = h[k];
#pragma unroll
        for (int q = 0; q < 4; q++) {
            float4 w = *reinterpret_cast<const float4*>(&w2[k][wofs + q * 4]);
            o[q * 4 + 0] = fmaf(hk, w.x, o[q * 4 + 0]);
            o[q * 4 + 1] = fmaf(hk, w.y, o[q * 4 + 1]);
            o[q * 4 + 2] = fmaf(hk, w.z, o[q * 4 + 2]);
            o[q * 4 + 3] = fmaf(hk, w.w, o[q * 4 + 3]);
        }
    }
    float* outp = side ? g_s2 : g_y2;
    float4* o4 = reinterpret_cast<float4*>(outp + (size_t)node * H);
#pragma unroll
    for (int q = 0; q < 4; q++)
        o4[q] = make_float4(o[q * 4], o[q * 4 + 1], o[q * 4 + 2], o[q * 4 + 3]);
}

// ---------------- h2 = acc2/cnt + b2 + s2 (no relu) ----------------------
__global__ void __launch_bounds__(256) k_h2(const float* __restrict__ b2) {
    __shared__ float sb2[H];
    int t = threadIdx.x;
    if (t < H) sb2[t] = b2[t];
    __syncthreads();

    int node = blockIdx.x * 256 + t;
    if (node >= N_NODES) return;

    float inv = 1.0f / fmaxf(g_cnt[node], 1.0f);
    const float4* a4 = reinterpret_cast<const float4*>(g_acc2 + (size_t)node * H);
    const float4* s4 = reinterpret_cast<const float4*>(g_s2  + (size_t)node * H);
    float4* o4 = reinterpret_cast<float4*>(g_h2 + (size_t)node * H);
#pragma unroll
    for (int q = 0; q < 4; q++) {
        float4 a = a4[q], s = s4[q];
        o4[q] = make_float4(a.x * inv + sb2[q * 4 + 0] + s.x,
                            a.y * inv + sb2[q * 4 + 1] + s.y,
                            a.z * inv + sb2[q * 4 + 2] + s.z,
                            a.w * inv + sb2[q * 4 + 3] + s.w);
    }
}

// ---------------- decode: sigmoid(<h2[i], h2[j]>), 2 threads/pair --------
__global__ void __launch_bounds__(256) k_decode(const void* __restrict__ div,
                                                int P, float* __restrict__ out) {
    int gid = blockIdx.x * blockDim.x + threadIdx.x;
    int p = gid >> 1;
    int s = gid & 1;
    if (p >= P) return;
    unsigned mask = __activemask();

    int idx;
    if (g_di64) {
        const long long* di = (const long long*)div;
        idx = (int)di[(size_t)s * P + p];
    } else {
        const int* di = (const int*)div;
        idx = di[(size_t)s * P + p];
    }

    const float4* r4 = reinterpret_cast<const float4*>(g_h2 + (size_t)idx * H);
    float4 v0 = r4[0], v1 = r4[1], v2 = r4[2], v3 = r4[3];
    float r[H] = {v0.x, v0.y, v0.z, v0.w, v1.x, v1.y, v1.z, v1.w,
                  v2.x, v2.y, v2.z, v2.w, v3.x, v3.y, v3.z, v3.w};

    // s==0 holds row a, s==1 holds row b.
    // s0 computes sum_{f<8} a[f]*b[f]; s1 computes sum_{f>=8} a[f]*b[f].
    float partial = 0.0f;
#pragma unroll
    for (int f = 0; f < 8; f++) {
        float sendv = s ? r[f] : r[f + 8];
        float other = __shfl_xor_sync(mask, sendv, 1);
        float mine  = s ? r[f + 8] : r[f];
        partial = fmaf(mine, other, partial);
    }
    float total = partial + __shfl_xor_sync(mask, partial, 1);
    if (s == 0) out[p] = 1.0f / (1.0f + __expf(-total));
}

// ---------------- launch ---------------------------------------------------
extern "C" void kernel_launch(void* const* d_in, const int* in_sizes, int n_in,
                              void* d_out, int out_size) {
    const float* x   = (const float*)d_in[0];
    const float* W1l = (const float*)d_in[1];
    const float* b1  = (const float*)d_in[2];
    const float* W1r = (const float*)d_in[3];
    const float* W2l = (const float*)d_in[4];
    const float* b2  = (const float*)d_in[5];
    const float* W2r = (const float*)d_in[6];
    const void*  ei  = d_in[7];
    const void*  di  = d_in[8];
    float* out = (float*)d_out;

    int E = in_sizes[7] / 2;
    int P = in_sizes[8] / 2;

    k_proj1  <<<(N_NODES + 255) / 256, 256>>>(x, W1l, W1r, (const int*)ei, (const int*)di);
    k_scatter1<<<(4LL * E + 255) / 256, 256>>>(ei, E);
    k_h1proj2<<<(2 * N_NODES + 255) / 256, 256>>>(b1, W2l, W2r);
    k_scatter2<<<(4LL * E + 255) / 256, 256>>>(ei, E);
    k_h2     <<<(N_NODES + 255) / 256, 256>>>(b2);
    k_decode <<<(2LL * P + 255) / 256, 256>>>(di, P, out);
}

// round 11
// speedup vs baseline: 1.3887x; 1.1736x over previous
#include <cuda_runtime.h>
#include <cuda_bf16.h>

#define N_NODES 100000
#define F_IN 128
#define H 16

// ---------------- device scratch (no allocations allowed) ----------------
__device__ __align__(16) float g_y1 [N_NODES * H];  // x @ W1l
__device__ __align__(16) float g_s1 [N_NODES * H];  // x @ W1r
__device__ __align__(16) float g_acc1[N_NODES * H];
__device__ __align__(16) float g_cnt [N_NODES];
__device__ __align__(16) float g_y2 [N_NODES * H];  // h1 @ W2l
__device__ __align__(16) float g_s2 [N_NODES * H];  // h1 @ W2r
__device__ __align__(16) float g_acc2[N_NODES * H];
__device__ __align__(16) unsigned int g_h2bf[N_NODES * 8];  // h2 as bf16x2 words

// index dtype flags: 1 if the corresponding index tensor is int64
__device__ int g_ei64;
__device__ int g_di64;

// sm_90+ vector reduction: 4 floats in one L2 atomic op
__device__ __forceinline__ void red_add_v4(float* addr, float4 v) {
    asm volatile("red.global.add.v4.f32 [%0], {%1, %2, %3, %4};"
                 :: "l"(addr), "f"(v.x), "f"(v.y), "f"(v.z), "f"(v.w)
                 : "memory");
}
__device__ __forceinline__ void red_add_f32(float* addr, float v) {
    asm volatile("red.global.add.f32 [%0], %1;"
                 :: "l"(addr), "f"(v) : "memory");
}

// packed f32x2 helpers (Blackwell FFMA2 — only reachable via PTX)
#define PACKF2(d, lo, hi) \
    asm("mov.b64 %0, {%1, %2};" : "=l"(d) : "f"(lo), "f"(hi))
#define UNPACKF2(lo, hi, v) \
    asm("mov.b64 {%0, %1}, %2;" : "=f"(lo), "=f"(hi) : "l"(v))
#define FMA2(acc, a, b) \
    asm("fma.rn.f32x2 %0, %1, %2, %0;" : "+l"(acc) : "l"(a), "l"(b))

// ---------------- proj1: y1 = x@W1l, s1 = x@W1r; zero acc1/cnt; probe ----
// Block: 256 threads, 256 nodes/block. Inner product in packed f32x2.
__global__ void __launch_bounds__(256) k_proj1(const float* __restrict__ x,
                                               const float* __restrict__ W1l,
                                               const float* __restrict__ W1r,
                                               const int* __restrict__ ei32,
                                               const int* __restrict__ di32) {
    __shared__ float wc[F_IN][32];   // [k][f], f in [0,32): L then R
    int t = threadIdx.x;

    // dtype probe: int64 non-negative -> odd 32-bit words are 0.
    if (blockIdx.x == 0 && t == 0) {
        int e64 = 1, d64 = 1;
#pragma unroll
        for (int k = 0; k < 16; k++) {
            if (ei32[2 * k + 1] != 0) e64 = 0;
            if (di32[2 * k + 1] != 0) d64 = 0;
        }
        g_ei64 = e64;
        g_di64 = d64;
    }

    // zero acc1 + cnt for this block's nodes
    {
        int node = blockIdx.x * 256 + t;
        if (node < N_NODES) {
            float4* a4 = reinterpret_cast<float4*>(g_acc1 + (size_t)node * H);
            float4 z = make_float4(0.f, 0.f, 0.f, 0.f);
            a4[0] = z; a4[1] = z; a4[2] = z; a4[3] = z;
            g_cnt[node] = 0.0f;
        }
    }

    // stage weights
    for (int i = t; i < F_IN * H; i += 256) {
        int k = i >> 4, f = i & 15;
        wc[k][f]      = W1l[i];
        wc[k][f + 16] = W1r[i];
    }
    __syncthreads();

    int fg = t & 3;            // output quad-group: fg*8 .. fg*8+7
    int ng = t >> 2;           // 0..63
    int node0 = (blockIdx.x * 64 + ng) * 4;

    bool v[4];
#pragma unroll
    for (int n = 0; n < 4; n++) v[n] = (node0 + n) < N_NODES;

    unsigned long long acc[4][4];   // 4 nodes x 4 f32x2 pairs (8 outputs)
#pragma unroll
    for (int n = 0; n < 4; n++)
#pragma unroll
        for (int j = 0; j < 4; j++) acc[n][j] = 0ULL;

    const float4* xp = reinterpret_cast<const float4*>(x);

    for (int k4 = 0; k4 < F_IN / 4; k4++) {
        float4 xv[4];
#pragma unroll
        for (int n = 0; n < 4; n++)
            xv[n] = v[n] ? xp[(size_t)(node0 + n) * (F_IN / 4) + k4]
                         : make_float4(0.f, 0.f, 0.f, 0.f);
#pragma unroll
        for (int kk = 0; kk < 4; kk++) {
            const float4 wA = *reinterpret_cast<const float4*>(&wc[k4 * 4 + kk][fg * 8]);
            const float4 wB = *reinterpret_cast<const float4*>(&wc[k4 * 4 + kk][fg * 8 + 4]);
            unsigned long long w01, w23, w45, w67;
            PACKF2(w01, wA.x, wA.y);
            PACKF2(w23, wA.z, wA.w);
            PACKF2(w45, wB.x, wB.y);
            PACKF2(w67, wB.z, wB.w);
#pragma unroll
            for (int n = 0; n < 4; n++) {
                float xs = (kk == 0) ? xv[n].x : (kk == 1) ? xv[n].y
                         : (kk == 2) ? xv[n].z : xv[n].w;
                unsigned long long xs2;
                PACKF2(xs2, xs, xs);
                FMA2(acc[n][0], xs2, w01);
                FMA2(acc[n][1], xs2, w23);
                FMA2(acc[n][2], xs2, w45);
                FMA2(acc[n][3], xs2, w67);
            }
        }
    }

#pragma unroll
    for (int n = 0; n < 4; n++) {
        if (!v[n]) continue;
        int node = node0 + n;
        float a0, a1, a2, a3, a4, a5, a6, a7;
        UNPACKF2(a0, a1, acc[n][0]);
        UNPACKF2(a2, a3, acc[n][1]);
        UNPACKF2(a4, a5, acc[n][2]);
        UNPACKF2(a6, a7, acc[n][3]);
        float* dst = (fg < 2) ? &g_y1[node * H + fg * 8]
                              : &g_s1[node * H + (fg - 2) * 8];
        float4* d4 = reinterpret_cast<float4*>(dst);
        d4[0] = make_float4(a0, a1, a2, a3);
        d4[1] = make_float4(a4, a5, a6, a7);
    }
}

// ---------------- scatter: 4 threads per edge ----------------------------
template<bool WITH_CNT>
__device__ __forceinline__ void scatter_body(const void* __restrict__ eiv, int E,
                                             const float* __restrict__ ysrc,
                                             float* __restrict__ adst) {
    int gid = blockIdx.x * blockDim.x + threadIdx.x;
    int e = gid >> 2;
    int q = gid & 3;
    if (e >= E) return;
    unsigned mask = __activemask();
    int lane = threadIdx.x & 31;

    int src = 0, dst = 0;
    if (q == 0) {
        if (g_ei64) {
            const long long* ei = (const long long*)eiv;
            src = (int)ei[e];
            dst = (int)ei[E + e];
        } else {
            const int* ei = (const int*)eiv;
            src = ei[e];
            dst = ei[E + e];
        }
    }
    src = __shfl_sync(mask, src, lane & ~3);
    dst = __shfl_sync(mask, dst, lane & ~3);

    float4 v = reinterpret_cast<const float4*>(ysrc)[(size_t)src * 4 + q];
    red_add_v4(adst + (size_t)dst * H + q * 4, v);
    if (WITH_CNT && q == 0) red_add_f32(&g_cnt[dst], 1.0f);
}

__global__ void __launch_bounds__(256) k_scatter1(const void* __restrict__ eiv, int E) {
    scatter_body<true>(eiv, E, g_y1, g_acc1);
}
__global__ void __launch_bounds__(256) k_scatter2(const void* __restrict__ eiv, int E) {
    scatter_body<false>(eiv, E, g_y2, g_acc2);
}

// ---- h1 = relu(acc1/cnt + b1 + s1); y2/s2 = h1@W2{l,r}; zero acc2 -------
__global__ void __launch_bounds__(256) k_h1proj2(const float* __restrict__ b1,
                                                 const float* __restrict__ W2l,
                                                 const float* __restrict__ W2r) {
    __shared__ float w2[H][32];   // [k][f]: L then R
    __shared__ float sb1[H];
    int t = threadIdx.x;
    {   // H*H = 256 == blockDim: each thread stages one entry of each matrix
        int k = t >> 4, f = t & 15;
        w2[k][f]      = W2l[t];
        w2[k][f + 16] = W2r[t];
    }
    if (t < H) sb1[t] = b1[t];
    __syncthreads();

    int gid = blockIdx.x * 256 + t;
    int node = gid >> 1;
    int side = gid & 1;
    if (node >= N_NODES) return;

    // zero acc2: each side zeroes half the node row
    {
        float4* a4 = reinterpret_cast<float4*>(g_acc2 + (size_t)node * H) + side * 2;
        float4 z = make_float4(0.f, 0.f, 0.f, 0.f);
        a4[0] = z; a4[1] = z;
    }

    float inv = 1.0f / fmaxf(g_cnt[node], 1.0f);
    const float4* a4 = reinterpret_cast<const float4*>(g_acc1 + (size_t)node * H);
    const float4* s4 = reinterpret_cast<const float4*>(g_s1  + (size_t)node * H);

    float h[H];
#pragma unroll
    for (int q = 0; q < 4; q++) {
        float4 a = a4[q], s = s4[q];
        h[q * 4 + 0] = fmaxf(a.x * inv + sb1[q * 4 + 0] + s.x, 0.0f);
        h[q * 4 + 1] = fmaxf(a.y * inv + sb1[q * 4 + 1] + s.y, 0.0f);
        h[q * 4 + 2] = fmaxf(a.z * inv + sb1[q * 4 + 2] + s.z, 0.0f);
        h[q * 4 + 3] = fmaxf(a.w * inv + sb1[q * 4 + 3] + s.w, 0.0f);
    }

    float o[H];
#pragma unroll
    for (int f = 0; f < H; f++) o[f] = 0.0f;
    int wofs = side * 16;
#pragma unroll
    for (int k = 0; k < H; k++) {
        float hk = h[k];
#pragma unroll
        for (int q = 0; q < 4; q++) {
            float4 w = *reinterpret_cast<const float4*>(&w2[k][wofs + q * 4]);
            o[q * 4 + 0] = fmaf(hk, w.x, o[q * 4 + 0]);
            o[q * 4 + 1] = fmaf(hk, w.y, o[q * 4 + 1]);
            o[q * 4 + 2] = fmaf(hk, w.z, o[q * 4 + 2]);
            o[q * 4 + 3] = fmaf(hk, w.w, o[q * 4 + 3]);
        }
    }
    float* outp = side ? g_s2 : g_y2;
    float4* o4 = reinterpret_cast<float4*>(outp + (size_t)node * H);
#pragma unroll
    for (int q = 0; q < 4; q++)
        o4[q] = make_float4(o[q * 4], o[q * 4 + 1], o[q * 4 + 2], o[q * 4 + 3]);
}

// ------- h2 = acc2/cnt + b2 + s2, stored as bf16 (decode-only consumer) --
__global__ void __launch_bounds__(256) k_h2(const float* __restrict__ b2) {
    __shared__ float sb2[H];
    int t = threadIdx.x;
    if (t < H) sb2[t] = b2[t];
    __syncthreads();

    int node = blockIdx.x * 256 + t;
    if (node >= N_NODES) return;

    float inv = 1.0f / fmaxf(g_cnt[node], 1.0f);
    const float4* a4 = reinterpret_cast<const float4*>(g_acc2 + (size_t)node * H);
    const float4* s4 = reinterpret_cast<const float4*>(g_s2  + (size_t)node * H);

    float h[H];
#pragma unroll
    for (int q = 0; q < 4; q++) {
        float4 a = a4[q], s = s4[q];
        h[q * 4 + 0] = a.x * inv + sb2[q * 4 + 0] + s.x;
        h[q * 4 + 1] = a.y * inv + sb2[q * 4 + 1] + s.y;
        h[q * 4 + 2] = a.z * inv + sb2[q * 4 + 2] + s.z;
        h[q * 4 + 3] = a.w * inv + sb2[q * 4 + 3] + s.w;
    }

    unsigned int w[8];
#pragma unroll
    for (int i = 0; i < 8; i++) {
        __nv_bfloat162 bb = __float22bfloat162_rn(make_float2(h[2 * i], h[2 * i + 1]));
        w[i] = *reinterpret_cast<unsigned int*>(&bb);
    }
    uint4* o4 = reinterpret_cast<uint4*>(g_h2bf + (size_t)node * 8);
    o4[0] = make_uint4(w[0], w[1], w[2], w[3]);
    o4[1] = make_uint4(w[4], w[5], w[6], w[7]);
}

// ---------------- decode: sigmoid(<h2[i], h2[j]>), 2 threads/pair --------
// h2 rows are bf16 (32B). bf16 -> f32 via bit shifts (ALU pipe, no CVT).
__global__ void __launch_bounds__(256) k_decode(const void* __restrict__ div,
                                                int P, float* __restrict__ out) {
    int gid = blockIdx.x * blockDim.x + threadIdx.x;
    int p = gid >> 1;
    int s = gid & 1;
    if (p >= P) return;
    unsigned mask = __activemask();

    int idx;
    if (g_di64) {
        const long long* di = (const long long*)div;
        idx = (int)di[(size_t)s * P + p];
    } else {
        const int* di = (const int*)div;
        idx = di[(size_t)s * P + p];
    }

    const uint4* r4 = reinterpret_cast<const uint4*>(g_h2bf + (size_t)idx * 8);
    uint4 u0 = r4[0], u1 = r4[1];
    unsigned int w[8] = {u0.x, u0.y, u0.z, u0.w, u1.x, u1.y, u1.z, u1.w};

    float r[H];
#pragma unroll
    for (int i = 0; i < 8; i++) {
        r[2 * i]     = __uint_as_float(w[i] << 16);
        r[2 * i + 1] = __uint_as_float(w[i] & 0xffff0000u);
    }

    // s==0 holds row a, s==1 holds row b.
    float partial = 0.0f;
#pragma unroll
    for (int f = 0; f < 8; f++) {
        float sendv = s ? r[f] : r[f + 8];
        float other = __shfl_xor_sync(mask, sendv, 1);
        float mine  = s ? r[f + 8] : r[f];
        partial = fmaf(mine, other, partial);
    }
    float total = partial + __shfl_xor_sync(mask, partial, 1);
    if (s == 0) out[p] = 1.0f / (1.0f + __expf(-total));
}

// ---------------- launch ---------------------------------------------------
extern "C" void kernel_launch(void* const* d_in, const int* in_sizes, int n_in,
                              void* d_out, int out_size) {
    const float* x   = (const float*)d_in[0];
    const float* W1l = (const float*)d_in[1];
    const float* b1  = (const float*)d_in[2];
    const float* W1r = (const float*)d_in[3];
    const float* W2l = (const float*)d_in[4];
    const float* b2  = (const float*)d_in[5];
    const float* W2r = (const float*)d_in[6];
    const void*  ei  = d_in[7];
    const void*  di  = d_in[8];
    float* out = (float*)d_out;

    int E = in_sizes[7] / 2;
    int P = in_sizes[8] / 2;

    k_proj1  <<<(N_NODES + 255) / 256, 256>>>(x, W1l, W1r, (const int*)ei, (const int*)di);
    k_scatter1<<<(4LL * E + 255) / 256, 256>>>(ei, E);
    k_h1proj2<<<(2 * N_NODES + 255) / 256, 256>>>(b1, W2l, W2r);
    k_scatter2<<<(4LL * E + 255) / 256, 256>>>(ei, E);
    k_h2     <<<(N_NODES + 255) / 256, 256>>>(b2);
    k_decode <<<(2LL * P + 255) / 256, 256>>>(di, P, out);
}

// round 12
// speedup vs baseline: 1.4197x; 1.0224x over previous
#include <cuda_runtime.h>
#include <cuda_bf16.h>

#define N_NODES 100000
#define F_IN 128
#define H 16

// ---------------- device scratch (no allocations allowed) ----------------
__device__ __align__(16) float g_y1 [N_NODES * H];  // x @ W1l
__device__ __align__(16) float g_s1 [N_NODES * H];  // x @ W1r
__device__ __align__(16) float g_acc1[N_NODES * H];
__device__ __align__(16) float g_cnt [N_NODES];
__device__ __align__(16) float g_y2 [N_NODES * H];  // h1 @ W2l
__device__ __align__(16) float g_s2 [N_NODES * H];  // h1 @ W2r
__device__ __align__(16) float g_acc2[N_NODES * H];
__device__ __align__(16) unsigned int g_h2bf[N_NODES * 8];  // h2 as bf16x2 words

// index dtype flags: 1 if the corresponding index tensor is int64
__device__ int g_ei64;
__device__ int g_di64;

// sm_90+ vector reduction: 4 floats in one L2 atomic op
__device__ __forceinline__ void red_add_v4(float* addr, float4 v) {
    asm volatile("red.global.add.v4.f32 [%0], {%1, %2, %3, %4};"
                 :: "l"(addr), "f"(v.x), "f"(v.y), "f"(v.z), "f"(v.w)
                 : "memory");
}
__device__ __forceinline__ void red_add_f32(float* addr, float v) {
    asm volatile("red.global.add.f32 [%0], %1;"
                 :: "l"(addr), "f"(v) : "memory");
}

// packed f32x2 helpers (Blackwell FFMA2 — only reachable via PTX)
#define PACKF2(d, lo, hi) \
    asm("mov.b64 %0, {%1, %2};" : "=l"(d) : "f"(lo), "f"(hi))
#define UNPACKF2(lo, hi, v) \
    asm("mov.b64 {%0, %1}, %2;" : "=f"(lo), "=f"(hi) : "l"(v))
#define FMA2(acc, a, b) \
    asm("fma.rn.f32x2 %0, %1, %2, %0;" : "+l"(acc) : "l"(a), "l"(b))

// ---------------- proj1: y1 = x@W1l, s1 = x@W1r; zero acc1/cnt; probe ----
// Block: 256 threads, 256 nodes/block. Inner product in packed f32x2.
__global__ void __launch_bounds__(256) k_proj1(const float* __restrict__ x,
                                               const float* __restrict__ W1l,
                                               const float* __restrict__ W1r,
                                               const int* __restrict__ ei32,
                                               const int* __restrict__ di32) {
    __shared__ float wc[F_IN][32];   // [k][f], f in [0,32): L then R
    int t = threadIdx.x;

    // dtype probe: int64 non-negative -> odd 32-bit words are 0.
    if (blockIdx.x == 0 && t == 0) {
        int e64 = 1, d64 = 1;
#pragma unroll
        for (int k = 0; k < 16; k++) {
            if (ei32[2 * k + 1] != 0) e64 = 0;
            if (di32[2 * k + 1] != 0) d64 = 0;
        }
        g_ei64 = e64;
        g_di64 = d64;
    }

    // zero acc1 + cnt for this block's nodes
    {
        int node = blockIdx.x * 256 + t;
        if (node < N_NODES) {
            float4* a4 = reinterpret_cast<float4*>(g_acc1 + (size_t)node * H);
            float4 z = make_float4(0.f, 0.f, 0.f, 0.f);
            a4[0] = z; a4[1] = z; a4[2] = z; a4[3] = z;
            g_cnt[node] = 0.0f;
        }
    }

    // stage weights
    for (int i = t; i < F_IN * H; i += 256) {
        int k = i >> 4, f = i & 15;
        wc[k][f]      = W1l[i];
        wc[k][f + 16] = W1r[i];
    }
    __syncthreads();

    int fg = t & 3;            // output quad-group: fg*8 .. fg*8+7
    int ng = t >> 2;           // 0..63
    int node0 = (blockIdx.x * 64 + ng) * 4;

    bool v[4];
#pragma unroll
    for (int n = 0; n < 4; n++) v[n] = (node0 + n) < N_NODES;

    unsigned long long acc[4][4];   // 4 nodes x 4 f32x2 pairs (8 outputs)
#pragma unroll
    for (int n = 0; n < 4; n++)
#pragma unroll
        for (int j = 0; j < 4; j++) acc[n][j] = 0ULL;

    const float4* xp = reinterpret_cast<const float4*>(x);

    for (int k4 = 0; k4 < F_IN / 4; k4++) {
        float4 xv[4];
#pragma unroll
        for (int n = 0; n < 4; n++)
            xv[n] = v[n] ? xp[(size_t)(node0 + n) * (F_IN / 4) + k4]
                         : make_float4(0.f, 0.f, 0.f, 0.f);
#pragma unroll
        for (int kk = 0; kk < 4; kk++) {
            const float4 wA = *reinterpret_cast<const float4*>(&wc[k4 * 4 + kk][fg * 8]);
            const float4 wB = *reinterpret_cast<const float4*>(&wc[k4 * 4 + kk][fg * 8 + 4]);
            unsigned long long w01, w23, w45, w67;
            PACKF2(w01, wA.x, wA.y);
            PACKF2(w23, wA.z, wA.w);
            PACKF2(w45, wB.x, wB.y);
            PACKF2(w67, wB.z, wB.w);
#pragma unroll
            for (int n = 0; n < 4; n++) {
                float xs = (kk == 0) ? xv[n].x : (kk == 1) ? xv[n].y
                         : (kk == 2) ? xv[n].z : xv[n].w;
                unsigned long long xs2;
                PACKF2(xs2, xs, xs);
                FMA2(acc[n][0], xs2, w01);
                FMA2(acc[n][1], xs2, w23);
                FMA2(acc[n][2], xs2, w45);
                FMA2(acc[n][3], xs2, w67);
            }
        }
    }

#pragma unroll
    for (int n = 0; n < 4; n++) {
        if (!v[n]) continue;
        int node = node0 + n;
        float a0, a1, a2, a3, a4, a5, a6, a7;
        UNPACKF2(a0, a1, acc[n][0]);
        UNPACKF2(a2, a3, acc[n][1]);
        UNPACKF2(a4, a5, acc[n][2]);
        UNPACKF2(a6, a7, acc[n][3]);
        float* dst = (fg < 2) ? &g_y1[node * H + fg * 8]
                              : &g_s1[node * H + (fg - 2) * 8];
        float4* d4 = reinterpret_cast<float4*>(dst);
        d4[0] = make_float4(a0, a1, a2, a3);
        d4[1] = make_float4(a4, a5, a6, a7);
    }
}

// ---------------- scatter: 4 edges per 4-lane group (MLP=4) --------------
// Lane q loads the (src,dst) pair of edge base_e+q (coalesced), handles the
// cnt-RED for its own edge, then a 4-iter loop shfl-broadcasts each edge's
// indices; lane q gathers/REDs quarter q of that edge's 16-float payload.
// All 4 gathers are independent -> 4-way MLP per thread.
template<bool WITH_CNT>
__device__ __forceinline__ void scatter_body(const void* __restrict__ eiv, int E,
                                             const float* __restrict__ ysrc,
                                             float* __restrict__ adst) {
    int gid = blockIdx.x * blockDim.x + threadIdx.x;
    int group = gid >> 2;
    int q = gid & 3;
    int base_e = group * 4;
    if (base_e >= E) return;             // uniform within the 4-lane group
    unsigned mask = __activemask();
    int lane = threadIdx.x & 31;
    int gbase = lane & ~3;

    int my_e = base_e + q;
    int my_e_cl = my_e < E ? my_e : E - 1;
    int src, dst;
    if (g_ei64) {
        const long long* ei = (const long long*)eiv;
        src = (int)ei[my_e_cl];
        dst = (int)ei[E + my_e_cl];
    } else {
        const int* ei = (const int*)eiv;
        src = ei[my_e_cl];
        dst = ei[E + my_e_cl];
    }
    if (WITH_CNT && my_e < E) red_add_f32(&g_cnt[dst], 1.0f);

#pragma unroll
    for (int j = 0; j < 4; j++) {
        int sj = __shfl_sync(mask, src, gbase + j);
        int dj = __shfl_sync(mask, dst, gbase + j);
        if (base_e + j < E) {
            float4 v = reinterpret_cast<const float4*>(ysrc)[(size_t)sj * 4 + q];
            red_add_v4(adst + (size_t)dj * H + q * 4, v);
        }
    }
}

__global__ void __launch_bounds__(256) k_scatter1(const void* __restrict__ eiv, int E) {
    scatter_body<true>(eiv, E, g_y1, g_acc1);
}
__global__ void __launch_bounds__(256) k_scatter2(const void* __restrict__ eiv, int E) {
    scatter_body<false>(eiv, E, g_y2, g_acc2);
}

// ---- h1 = relu(acc1/cnt + b1 + s1); y2/s2 = h1@W2{l,r}; zero acc2 -------
__global__ void __launch_bounds__(256) k_h1proj2(const float* __restrict__ b1,
                                                 const float* __restrict__ W2l,
                                                 const float* __restrict__ W2r) {
    __shared__ float w2[H][32];   // [k][f]: L then R
    __shared__ float sb1[H];
    int t = threadIdx.x;
    {   // H*H = 256 == blockDim: each thread stages one entry of each matrix
        int k = t >> 4, f = t & 15;
        w2[k][f]      = W2l[t];
        w2[k][f + 16] = W2r[t];
    }
    if (t < H) sb1[t] = b1[t];
    __syncthreads();

    int gid = blockIdx.x * 256 + t;
    int node = gid >> 1;
    int side = gid & 1;
    if (node >= N_NODES) return;

    // zero acc2: each side zeroes half the node row
    {
        float4* a4 = reinterpret_cast<float4*>(g_acc2 + (size_t)node * H) + side * 2;
        float4 z = make_float4(0.f, 0.f, 0.f, 0.f);
        a4[0] = z; a4[1] = z;
    }

    float inv = 1.0f / fmaxf(g_cnt[node], 1.0f);
    const float4* a4 = reinterpret_cast<const float4*>(g_acc1 + (size_t)node * H);
    const float4* s4 = reinterpret_cast<const float4*>(g_s1  + (size_t)node * H);

    float h[H];
#pragma unroll
    for (int q = 0; q < 4; q++) {
        float4 a = a4[q], s = s4[q];
        h[q * 4 + 0] = fmaxf(a.x * inv + sb1[q * 4 + 0] + s.x, 0.0f);
        h[q * 4 + 1] = fmaxf(a.y * inv + sb1[q * 4 + 1] + s.y, 0.0f);
        h[q * 4 + 2] = fmaxf(a.z * inv + sb1[q * 4 + 2] + s.z, 0.0f);
        h[q * 4 + 3] = fmaxf(a.w * inv + sb1[q * 4 + 3] + s.w, 0.0f);
    }

    float o[H];
#pragma unroll
    for (int f = 0; f < H; f++) o[f] = 0.0f;
    int wofs = side * 16;
#pragma unroll
    for (int k = 0; k < H; k++) {
        float hk = h[k];
#pragma unroll
        for (int q = 0; q < 4; q++) {
            float4 w = *reinterpret_cast<const float4*>(&w2[k][wofs + q * 4]);
            o[q * 4 + 0] = fmaf(hk, w.x, o[q * 4 + 0]);
            o[q * 4 + 1] = fmaf(hk, w.y, o[q * 4 + 1]);
            o[q * 4 + 2] = fmaf(hk, w.z, o[q * 4 + 2]);
            o[q * 4 + 3] = fmaf(hk, w.w, o[q * 4 + 3]);
        }
    }
    float* outp = side ? g_s2 : g_y2;
    float4* o4 = reinterpret_cast<float4*>(outp + (size_t)node * H);
#pragma unroll
    for (int q = 0; q < 4; q++)
        o4[q] = make_float4(o[q * 4], o[q * 4 + 1], o[q * 4 + 2], o[q * 4 + 3]);
}

// ------- h2 = acc2/cnt + b2 + s2, stored as bf16 (decode-only consumer) --
__global__ void __launch_bounds__(256) k_h2(const float* __restrict__ b2) {
    __shared__ float sb2[H];
    int t = threadIdx.x;
    if (t < H) sb2[t] = b2[t];
    __syncthreads();

    int node = blockIdx.x * 256 + t;
    if (node >= N_NODES) return;

    float inv = 1.0f / fmaxf(g_cnt[node], 1.0f);
    const float4* a4 = reinterpret_cast<const float4*>(g_acc2 + (size_t)node * H);
    const float4* s4 = reinterpret_cast<const float4*>(g_s2  + (size_t)node * H);

    float h[H];
#pragma unroll
    for (int q = 0; q < 4; q++) {
        float4 a = a4[q], s = s4[q];
        h[q * 4 + 0] = a.x * inv + sb2[q * 4 + 0] + s.x;
        h[q * 4 + 1] = a.y * inv + sb2[q * 4 + 1] + s.y;
        h[q * 4 + 2] = a.z * inv + sb2[q * 4 + 2] + s.z;
        h[q * 4 + 3] = a.w * inv + sb2[q * 4 + 3] + s.w;
    }

    unsigned int w[8];
#pragma unroll
    for (int i = 0; i < 8; i++) {
        __nv_bfloat162 bb = __float22bfloat162_rn(make_float2(h[2 * i], h[2 * i + 1]));
        w[i] = *reinterpret_cast<unsigned int*>(&bb);
    }
    uint4* o4 = reinterpret_cast<uint4*>(g_h2bf + (size_t)node * 8);
    o4[0] = make_uint4(w[0], w[1], w[2], w[3]);
    o4[1] = make_uint4(w[4], w[5], w[6], w[7]);
}

// ---------------- decode: sigmoid(<h2[i], h2[j]>), 2 threads/pair --------
// h2 rows are bf16 (32B). bf16 -> f32 via bit shifts (ALU pipe, no CVT).
__global__ void __launch_bounds__(256) k_decode(const void* __restrict__ div,
                                                int P, float* __restrict__ out) {
    int gid = blockIdx.x * blockDim.x + threadIdx.x;
    int p = gid >> 1;
    int s = gid & 1;
    if (p >= P) return;
    unsigned mask = __activemask();

    int idx;
    if (g_di64) {
        const long long* di = (const long long*)div;
        idx = (int)di[(size_t)s * P + p];
    } else {
        const int* di = (const int*)div;
        idx = di[(size_t)s * P + p];
    }

    const uint4* r4 = reinterpret_cast<const uint4*>(g_h2bf + (size_t)idx * 8);
    uint4 u0 = r4[0], u1 = r4[1];
    unsigned int w[8] = {u0.x, u0.y, u0.z, u0.w, u1.x, u1.y, u1.z, u1.w};

    float r[H];
#pragma unroll
    for (int i = 0; i < 8; i++) {
        r[2 * i]     = __uint_as_float(w[i] << 16);
        r[2 * i + 1] = __uint_as_float(w[i] & 0xffff0000u);
    }

    // s==0 holds row a, s==1 holds row b.
    float partial = 0.0f;
#pragma unroll
    for (int f = 0; f < 8; f++) {
        float sendv = s ? r[f] : r[f + 8];
        float other = __shfl_xor_sync(mask, sendv, 1);
        float mine  = s ? r[f + 8] : r[f];
        partial = fmaf(mine, other, partial);
    }
    float total = partial + __shfl_xor_sync(mask, partial, 1);
    if (s == 0) out[p] = 1.0f / (1.0f + __expf(-total));
}

// ---------------- launch ---------------------------------------------------
extern "C" void kernel_launch(void* const* d_in, const int* in_sizes, int n_in,
                              void* d_out, int out_size) {
    const float* x   = (const float*)d_in[0];
    const float* W1l = (const float*)d_in[1];
    const float* b1  = (const float*)d_in[2];
    const float* W1r = (const float*)d_in[3];
    const float* W2l = (const float*)d_in[4];
    const float* b2  = (const float*)d_in[5];
    const float* W2r = (const float*)d_in[6];
    const void*  ei  = d_in[7];
    const void*  di  = d_in[8];
    float* out = (float*)d_out;

    int E = in_sizes[7] / 2;
    int P = in_sizes[8] / 2;

    long long sthreads = ((long long)(E + 3) / 4) * 4;   // one thread per edge, 4-lane groups
    int sblocks = (int)((sthreads + 255) / 256);

    k_proj1  <<<(N_NODES + 255) / 256, 256>>>(x, W1l, W1r, (const int*)ei, (const int*)di);
    k_scatter1<<<sblocks, 256>>>(ei, E);
    k_h1proj2<<<(2 * N_NODES + 255) / 256, 256>>>(b1, W2l, W2r);
    k_scatter2<<<sblocks, 256>>>(ei, E);
    k_h2     <<<(N_NODES + 255) / 256, 256>>>(b2);
    k_decode <<<(2LL * P + 255) / 256, 256>>>(di, P, out);
}